// round 5
// baseline (speedup 1.0000x reference)
#include <cuda_runtime.h>
#include <cuda_fp16.h>
#include <cstdint>
#include <math.h>

// Problem dims
#define PP 81
#define EE 256
#define HH 4096
#define G4 16384          // 4*HH

// Main-loop config
#define NB 128            // persistent blocks (all co-resident)
#define NT 512            // threads per block (16 warps)
#define UPB 32            // units per block
#define ROWS_PER_BLK 128  // 4 gates * UPB

// Streaming pipeline
#define NSTAGE 32                 // matrix stages per step (4096/128)
#define SEG 128                   // halves per row per stage
#define SD 6                      // ring depth (stages in flight)
#define STAGE_BYTES (16 * 8 * SEG * 2)      // 16 warps * 8 rows * 256B = 32768
#define RING_BYTES (SD * STAGE_BYTES)       // 196608
#define SMEM_TOTAL (RING_BYTES + HH * 4 + ROWS_PER_BLK * 4)  // +h_sh +z_sh

// ---------------- scratch ----------------------------------------------------
__device__ __half d_Mt[(size_t)G4 * HH];  // 128 MB: Mt[k][j] = W[E+j][k] + U[j][k]
__device__ float  d_X[(size_t)PP * G4];   // X[t][k] = b[k] + x_t @ W[:E]
__device__ float  d_hbuf[2][HH];          // ping-pong hidden state
__device__ unsigned d_bar_count;
__device__ unsigned d_bar_gen;

// ---------------- kernel A: build Mt = (W[E:,:] + U)^T  (fp16) ---------------
__global__ void build_Mt_kernel(const float* __restrict__ W,
                                const float* __restrict__ U) {
    __shared__ float tile[32][33];
    int k0 = blockIdx.x * 32;
    int j0 = blockIdx.y * 32;
    #pragma unroll
    for (int r = threadIdx.y; r < 32; r += 8) {
        int j = j0 + r;
        int k = k0 + threadIdx.x;
        tile[r][threadIdx.x] = W[(size_t)(EE + j) * G4 + k] + U[(size_t)j * G4 + k];
    }
    __syncthreads();
    #pragma unroll
    for (int r = threadIdx.y; r < 32; r += 8) {
        int k = k0 + r;
        int j = j0 + threadIdx.x;
        d_Mt[(size_t)k * HH + j] = __float2half_rn(tile[threadIdx.x][r]);
    }
}

// ---------------- kernel B: X = b + h_enc @ W[:E]  (W read 3x, not 81x) ------
#define TCH 27   // t-chunk (81 = 3*27)
__global__ void build_X_kernel(const float* __restrict__ h_enc,
                               const float* __restrict__ W,
                               const float* __restrict__ b) {
    int k = blockIdx.x * 128 + threadIdx.x;
    int t0 = blockIdx.y * TCH;
    float acc[TCH];
    float bb = b[k];
    #pragma unroll
    for (int t = 0; t < TCH; t++) acc[t] = bb;
    for (int e = 0; e < EE; e++) {
        float w = W[(size_t)e * G4 + k];
        #pragma unroll
        for (int t = 0; t < TCH; t++)
            acc[t] = fmaf(__ldg(&h_enc[(t0 + t) * EE + e]), w, acc[t]);
    }
    #pragma unroll
    for (int t = 0; t < TCH; t++) d_X[(size_t)(t0 + t) * G4 + k] = acc[t];
}

// ---------------- kernel C: h_buf[0] = h0 -------------------------------------
__global__ void init_h_kernel(const float* __restrict__ h0) {
    int i = blockIdx.x * 256 + threadIdx.x;
    if (i < HH) d_hbuf[0][i] = h0[i];
}

// ---------------- grid barrier ------------------------------------------------
__device__ __forceinline__ void grid_barrier() {
    __syncthreads();
    if (threadIdx.x == 0) {
        volatile unsigned* vgen = &d_bar_gen;
        unsigned gen = *vgen;
        __threadfence();
        if (atomicAdd(&d_bar_count, 1u) == NB - 1) {
            d_bar_count = 0;
            __threadfence();
            *vgen = gen + 1;
        } else {
            while (*vgen == gen) { }
            __threadfence();
        }
    }
    __syncthreads();
}

// ---------------- cp.async helpers ---------------------------------------------
__device__ __forceinline__ void cp16(uint32_t dst_smem, const void* src) {
    asm volatile("cp.async.cg.shared.global [%0], [%1], 16;\n"
                 :: "r"(dst_smem), "l"(src));
}
__device__ __forceinline__ void cp_commit() {
    asm volatile("cp.async.commit_group;\n" ::: "memory");
}
__device__ __forceinline__ void cp_wait() {
    asm volatile("cp.async.wait_group %0;\n" :: "n"(SD - 1) : "memory");
}

// ---------------- kernel D: persistent LSTM loop, cp.async streaming ----------
__global__ void __launch_bounds__(NT, 1)
lstm_loop_kernel(float* __restrict__ orders) {
    extern __shared__ char smem_dyn[];
    char*  ring = smem_dyn;
    float* h_sh = (float*)(smem_dyn + RING_BYTES);
    float* z_sh = h_sh + HH;

    const int tid  = threadIdx.x;
    const int warp = tid >> 5;
    const int lane = tid & 31;
    const int hi   = lane >> 4;       // 0/1: which row parity this lane copies
    const int part = lane & 15;       // 16B chunk within 256B row-segment
    const int ub   = blockIdx.x * UPB;

    const uint32_t ring_s = (uint32_t)__cvta_generic_to_shared(ring);

    // Global source base for the 4 rows this lane copies (k = 2c+hi),
    // INCLUDING this lane's 16B part offset within each 256B segment.
    const char* gsrc[4];
    #pragma unroll
    for (int c = 0; c < 4; c++) {
        int k = 2 * c + hi;
        int r = warp + 16 * k;                // row 0..127
        int q = r >> 5, u = r & 31;           // gate, unit
        gsrc[c] = (const char*)(d_Mt + (size_t)(q * HH + ub + u) * HH)
                + (size_t)(part * 16);        // <-- per-lane part offset (R4 bugfix)
    }

    float c_reg = 0.0f;

    // ---- prologue: fill ring with matrix stages 0..SD-1
    #pragma unroll
    for (int gsp = 0; gsp < SD; gsp++) {
        uint32_t dst_base = ring_s + (uint32_t)(gsp * STAGE_BYTES)
                          + (uint32_t)(warp * 8 * 256) + (uint32_t)(part * 16);
        #pragma unroll
        for (int c = 0; c < 4; c++) {
            int k = 2 * c + hi;
            cp16(dst_base + (uint32_t)(k * 256), gsrc[c] + (size_t)gsp * 256);
        }
        cp_commit();
    }

    int slot = 0;         // ring slot of current stage (gs % SD)
    int m_issue = SD;     // matrix stage index to issue next (mod NSTAGE)
    long gs = 0;          // global stage counter
    const long GS_TOTAL = (long)PP * NSTAGE;

    for (int t = 0; t < PP; t++) {
        const float* __restrict__ hg = d_hbuf[t & 1];

        // load current h into smem
        {
            float4* h4s = (float4*)h_sh;
            const float4* hg4 = (const float4*)hg;
            #pragma unroll
            for (int i = tid; i < HH / 4; i += NT) h4s[i] = hg4[i];
        }
        __syncthreads();

        // emit pre-update h
        if (tid < UPB) orders[(size_t)t * HH + ub + tid] = h_sh[ub + tid];

        float acc[8];
        #pragma unroll
        for (int k = 0; k < 8; k++) acc[k] = 0.0f;

        const float4* __restrict__ h4 = (const float4*)h_sh;

        // ---- 32 stages; per-warp pipeline, no block syncs ----
        for (int s = 0; s < NSTAGE; s++) {
            cp_wait();
            __syncwarp();

            const char* tbase = ring + (size_t)slot * STAGE_BYTES
                              + (size_t)warp * 8 * 256 + (size_t)lane * 8;
            float4 hv = h4[s * (SEG / 4) + lane];
            #pragma unroll
            for (int k = 0; k < 8; k++) {
                uint2 raw = *(const uint2*)(tbase + k * 256);
                half2 p0 = *(half2*)&raw.x;
                half2 p1 = *(half2*)&raw.y;
                float2 f0 = __half22float2(p0);
                float2 f1 = __half22float2(p1);
                float a = acc[k];
                a = fmaf(f0.x, hv.x, a);
                a = fmaf(f0.y, hv.y, a);
                a = fmaf(f1.x, hv.z, a);
                a = fmaf(f1.y, hv.w, a);
                acc[k] = a;
            }

            // issue stage gs+SD into the slot just consumed
            if (gs + SD < GS_TOTAL) {
                uint32_t dst_base = ring_s + (uint32_t)(slot * STAGE_BYTES)
                                  + (uint32_t)(warp * 8 * 256) + (uint32_t)(part * 16);
                #pragma unroll
                for (int c = 0; c < 4; c++) {
                    int k = 2 * c + hi;
                    cp16(dst_base + (uint32_t)(k * 256),
                         gsrc[c] + (size_t)m_issue * 256);
                }
            }
            cp_commit();   // always commit (empty group ok) to keep counts uniform

            gs++;
            slot = (slot + 1 == SD) ? 0 : slot + 1;
            m_issue = (m_issue + 1 == NSTAGE) ? 0 : m_issue + 1;
        }

        // reduce accumulators: row r = warp + 16k -> z_sh[r]
        #pragma unroll
        for (int k = 0; k < 8; k++) {
            float a = acc[k];
            #pragma unroll
            for (int sft = 16; sft; sft >>= 1)
                a += __shfl_xor_sync(0xFFFFFFFFu, a, sft);
            if (lane == 0) z_sh[warp + 16 * k] = a;
        }
        __syncthreads();

        // gate math + state update
        if (tid < UPB) {
            int u = tid;
            const float* Xt = d_X + (size_t)t * G4;
            float zi = z_sh[0 * UPB + u] + Xt[0 * HH + ub + u];
            float zf = z_sh[1 * UPB + u] + Xt[1 * HH + ub + u];
            float zg = z_sh[2 * UPB + u] + Xt[2 * HH + ub + u];
            float zo = z_sh[3 * UPB + u] + Xt[3 * HH + ub + u];
            float gi = 1.0f / (1.0f + expf(-zi));
            float gf = 1.0f / (1.0f + expf(-zf));
            float go = 1.0f / (1.0f + expf(-zo));
            float cn = gf * c_reg + gi * zg;
            float hn = go * cn;
            c_reg = cn;
            d_hbuf[(t + 1) & 1][ub + u] = hn;
            __threadfence();
        }

        grid_barrier();
    }
}

// ---------------- launch --------------------------------------------------------
extern "C" void kernel_launch(void* const* d_in, const int* in_sizes, int n_in,
                              void* d_out, int out_size) {
    const float* h_enc = (const float*)d_in[0];  // [81,256]
    const float* h0    = (const float*)d_in[1];  // [4096]
    const float* W     = (const float*)d_in[2];  // [4352,16384]
    const float* U     = (const float*)d_in[3];  // [4096,16384]
    const float* b     = (const float*)d_in[4];  // [16384]
    float* orders = (float*)d_out;               // [81,4096]

    static int smem_set = 0;
    if (!smem_set) {
        cudaFuncSetAttribute(lstm_loop_kernel,
                             cudaFuncAttributeMaxDynamicSharedMemorySize,
                             SMEM_TOTAL);
        smem_set = 1;
    }

    build_Mt_kernel<<<dim3(G4 / 32, HH / 32), dim3(32, 8)>>>(W, U);
    build_X_kernel<<<dim3(G4 / 128, 3), 128>>>(h_enc, W, b);
    init_h_kernel<<<(HH + 255) / 256, 256>>>(h0);
    lstm_loop_kernel<<<NB, NT, SMEM_TOTAL>>>(orders);
}